// round 14
// baseline (speedup 1.0000x reference)
#include <cuda_runtime.h>
#include <cuda_fp16.h>
#include <cstdint>

// Problem constants
#define T_TOK 4096
#define D_DIM 1024
#define E_NUM 8
#define F_DIM 4096
#define NSLOT (T_TOK * 2)
#define PAD_ROWS 256

// GEMM config: 128x128 CTA tile, 128 threads (4 warps, warp tile 64x64), 2 CTAs/SM
#define BM 128
#define BN 128
#define BK 32
#define SA 40
#define NTHR 128
#define A_TILE_B (BM * SA * 2)     // 10240 B
#define B_TILE_B (BN * SA * 2)     // 10240 B
#define STAGE_B (A_TILE_B + B_TILE_B)  // 20480 B
#define NSTAGE 3
#define SMEM_ALLOC (NSTAGE * STAGE_B + 1024)   // 62464 B

// ---------------- static scratch ----------------
__device__ __half g_xg[(size_t)(NSLOT + PAD_ROWS) * D_DIM];
__device__ __half g_h[(size_t)(NSLOT + PAD_ROWS) * F_DIM];
__device__ __half g_w1h[(size_t)E_NUM * F_DIM * D_DIM];
__device__ __half g_w2h[(size_t)E_NUM * D_DIM * F_DIM];
__device__ int    g_tok_e[NSLOT];
__device__ float  g_tok_g[NSLOT];
__device__ int    g_counts[E_NUM];
__device__ int    g_offsets[E_NUM];
__device__ int    g_token_of_slot[NSLOT];
__device__ float  g_gate_of_slot[NSLOT];

__device__ __forceinline__ float siluf(float v) { return v / (1.f + __expf(-v)); }

// ---------------- PTX helpers ----------------
__device__ __forceinline__ void cp16(uint32_t dst, const void* src) {
    asm volatile("cp.async.cg.shared.global [%0], [%1], 16;\n" :: "r"(dst), "l"(src));
}
__device__ __forceinline__ void cp_commit() { asm volatile("cp.async.commit_group;\n"); }
template <int N> __device__ __forceinline__ void cp_wait() {
    asm volatile("cp.async.wait_group %0;\n" :: "n"(N));
}
__device__ __forceinline__ void ldm_x4(uint32_t r[4], uint32_t addr) {
    asm volatile("ldmatrix.sync.aligned.m8n8.x4.shared.b16 {%0,%1,%2,%3}, [%4];"
                 : "=r"(r[0]), "=r"(r[1]), "=r"(r[2]), "=r"(r[3]) : "r"(addr));
}
__device__ __forceinline__ void mma16816(float c[4],
                                         const uint32_t a[4],
                                         const uint32_t b[2]) {
    asm volatile(
        "mma.sync.aligned.m16n8k16.row.col.f32.f16.f16.f32 "
        "{%0,%1,%2,%3}, {%4,%5,%6,%7}, {%8,%9}, {%0,%1,%2,%3};\n"
        : "+f"(c[0]), "+f"(c[1]), "+f"(c[2]), "+f"(c[3])
        : "r"(a[0]), "r"(a[1]), "r"(a[2]), "r"(a[3]), "r"(b[0]), "r"(b[1]));
}

// ---------------- kernel 1: router ----------------
__global__ void k_router(const float* __restrict__ x,
                         const float* __restrict__ Wr,
                         const float* __restrict__ br) {
    int warp = threadIdx.x >> 5, lane = threadIdx.x & 31;
    int t = blockIdx.x * 8 + warp;
    if (t >= T_TOK) return;

    const float4* xr = (const float4*)(x + (size_t)t * D_DIM);
    float acc[E_NUM];
#pragma unroll
    for (int e = 0; e < E_NUM; e++) acc[e] = 0.f;

    for (int i = lane; i < D_DIM / 4; i += 32) {
        float4 xv = xr[i];
#pragma unroll
        for (int e = 0; e < E_NUM; e++) {
            float4 wv = ((const float4*)(Wr + (size_t)e * D_DIM))[i];
            acc[e] += xv.x * wv.x + xv.y * wv.y + xv.z * wv.z + xv.w * wv.w;
        }
    }
#pragma unroll
    for (int e = 0; e < E_NUM; e++) {
#pragma unroll
        for (int off = 16; off > 0; off >>= 1)
            acc[e] += __shfl_down_sync(0xffffffffu, acc[e], off);
    }
    if (lane == 0) {
        float l[E_NUM];
#pragma unroll
        for (int e = 0; e < E_NUM; e++) l[e] = acc[e] + br[e];
        int i1 = 0;
#pragma unroll
        for (int e = 1; e < E_NUM; e++) if (l[e] > l[i1]) i1 = e;
        int i2 = (i1 == 0) ? 1 : 0;
#pragma unroll
        for (int e = 0; e < E_NUM; e++)
            if (e != i1 && l[e] > l[i2]) i2 = e;
        float d  = l[i2] - l[i1];
        float e2 = __expf(d);
        float inv = 1.f / (1.f + e2);
        g_tok_e[2 * t]     = i1; g_tok_g[2 * t]     = inv;
        g_tok_e[2 * t + 1] = i2; g_tok_g[2 * t + 1] = e2 * inv;
    }
}

// ---------------- kernel 2: sched (counts + offsets + assign; 1 block) -----
__global__ void k_sched() {
    __shared__ int cnt[E_NUM], offs[E_NUM], cur[E_NUM];
    int tid = threadIdx.x;
    if (tid < E_NUM) { cnt[tid] = 0; cur[tid] = 0; }
    __syncthreads();
    for (int s = tid; s < NSLOT; s += blockDim.x)
        atomicAdd(&cnt[g_tok_e[s]], 1);
    __syncthreads();
    if (tid == 0) {
        int o = 0;
        for (int e = 0; e < E_NUM; e++) {
            offs[e] = o;
            g_offsets[e] = o;
            g_counts[e] = cnt[e];
            o += cnt[e];
        }
    }
    __syncthreads();
    for (int t = tid; t < T_TOK; t += blockDim.x) {
#pragma unroll
        for (int j = 0; j < 2; j++) {
            int e = g_tok_e[2 * t + j];
            int p = atomicAdd(&cur[e], 1);
            int slot = offs[e] + p;
            g_token_of_slot[slot] = t;
            g_gate_of_slot[slot]  = g_tok_g[2 * t + j];
        }
    }
}

// ---------------- kernel 3: prep (zero out + gather + W1 convert) ----------
__global__ __launch_bounds__(256) void k_prep(const float* __restrict__ x,
                                              const float* __restrict__ W1,
                                              float* __restrict__ out) {
    int b = blockIdx.x, tid = threadIdx.x;
    if (tid < 128)
        ((float4*)out)[(size_t)b * 128 + tid] = make_float4(0.f, 0.f, 0.f, 0.f);
    {
        int tok = g_token_of_slot[b];
        float4 v = ((const float4*)(x + (size_t)tok * D_DIM))[tid];
        __half2 lo = __floats2half2_rn(v.x, v.y);
        __half2 hi = __floats2half2_rn(v.z, v.w);
        uint2 u; u.x = *(uint32_t*)&lo; u.y = *(uint32_t*)&hi;
        ((uint2*)(g_xg + (size_t)b * D_DIM))[tid] = u;
    }
#pragma unroll
    for (int j = 0; j < 4; j++) {
        size_t i = (size_t)b * 1024 + j * 256 + tid;
        float4 v = ((const float4*)W1)[i];
        __half2 lo = __floats2half2_rn(v.x, v.y);
        __half2 hi = __floats2half2_rn(v.z, v.w);
        uint2 u; u.x = *(uint32_t*)&lo; u.y = *(uint32_t*)&hi;
        ((uint2*)g_w1h)[i] = u;
    }
}

// ---------------- kernel 5: convert W2 ----------------
__global__ __launch_bounds__(256) void k_cw2(const float* __restrict__ W2) {
    size_t n4 = (size_t)E_NUM * D_DIM * F_DIM / 4;
    for (size_t i = (size_t)blockIdx.x * blockDim.x + threadIdx.x; i < n4;
         i += (size_t)gridDim.x * blockDim.x) {
        float4 v = ((const float4*)W2)[i];
        __half2 lo = __floats2half2_rn(v.x, v.y);
        __half2 hi = __floats2half2_rn(v.z, v.w);
        uint2 u; u.x = *(uint32_t*)&lo; u.y = *(uint32_t*)&hi;
        ((uint2*)g_w2h)[i] = u;
    }
}

// ---------------- GEMM core ----------------
// fill one stage: A (128 x 32 halves) + B (128 x 32 halves), rows padded SA=40
__device__ __forceinline__ void fill_stage(uint32_t sbase,
                                           const __half* A, const __half* Bw,
                                           int k0, int ldk, int tid) {
#pragma unroll
    for (int it = 0; it < 4; it++) {
        int i = tid + it * NTHR;          // 0..511
        int r = i >> 2, c = i & 3;
        cp16(sbase + (uint32_t)(r * SA + c * 8) * 2,
             A + (size_t)r * ldk + k0 + c * 8);
    }
#pragma unroll
    for (int it = 0; it < 4; it++) {
        int i = tid + it * NTHR;
        int r = i >> 2, c = i & 3;
        cp16(sbase + A_TILE_B + (uint32_t)(r * SA + c * 8) * 2,
             Bw + (size_t)r * ldk + k0 + c * 8);
    }
}

// compute one BK=32 stage; warp tile 64x64 (4 warps: 2m x 2n)
__device__ __forceinline__ void compute_stage(uint32_t sbase, int mbase, int nbase,
                                              int rowsel, int khalf16,
                                              float acc[4][8][4]) {
    uint32_t abase = sbase, bbase = sbase + A_TILE_B;
#pragma unroll
    for (int kk = 0; kk < 2; kk++) {
        int kbyte = kk * 32 + khalf16;
        uint32_t a[4][4];
#pragma unroll
        for (int mt = 0; mt < 4; mt++) {
            int row = mbase + mt * 16 + rowsel;
            ldm_x4(a[mt], abase + row * (SA * 2) + kbyte);
        }
        uint32_t b[8][2];
#pragma unroll
        for (int ntp = 0; ntp < 4; ntp++) {
            int row = nbase + ntp * 16 + rowsel;
            uint32_t t[4];
            ldm_x4(t, bbase + row * (SA * 2) + kbyte);
            b[2 * ntp][0] = t[0]; b[2 * ntp + 1][0] = t[1];
            b[2 * ntp][1] = t[2]; b[2 * ntp + 1][1] = t[3];
        }
#pragma unroll
        for (int mt = 0; mt < 4; mt++)
#pragma unroll
            for (int nt = 0; nt < 8; nt++)
                mma16816(acc[mt][nt], a[mt], b[nt]);
    }
}

// 3-stage, one __syncthreads per K-step (R8-proven schedule)
__device__ __forceinline__ void gemm_mainloop(uint32_t s0,
                                              const __half* A, const __half* Bw,
                                              int ldk, int NK, int tid,
                                              int mbase, int nbase,
                                              int rowsel, int khalf16,
                                              float acc[4][8][4]) {
    fill_stage(s0, A, Bw, 0, ldk, tid);
    cp_commit();
    fill_stage(s0 + STAGE_B, A, Bw, BK, ldk, tid);
    cp_commit();
    int buf = 0;
    for (int it = 0; it < NK; it++) {
        if (it + 1 < NK) cp_wait<1>(); else cp_wait<0>();
        __syncthreads();
        if (it + 2 < NK) {
            int nb = buf + 2; if (nb >= NSTAGE) nb -= NSTAGE;
            fill_stage(s0 + nb * STAGE_B, A, Bw, (it + 2) * BK, ldk, tid);
            cp_commit();
        }
        compute_stage(s0 + buf * STAGE_B, mbase, nbase, rowsel, khalf16, acc);
        buf++; if (buf == NSTAGE) buf = 0;
    }
}

// ---------------- kernel 4: GEMM1  h = silu(xg @ W1h^T + b1) ----------------
__global__ __launch_bounds__(NTHR, 2) void k_gemm1(const float* __restrict__ b1) {
    int e   = blockIdx.z;
    int len = g_counts[e];
    int m0  = blockIdx.y * BM;
    if (m0 >= len) return;
    int n0  = blockIdx.x * BN;
    int off = g_offsets[e];

    extern __shared__ char smraw[];
    __shared__ float sbias[BN];
    uint32_t s0 = (uint32_t)__cvta_generic_to_shared(smraw);
    s0 = (s0 + 1023u) & ~1023u;

    int tid = threadIdx.x, warp = tid >> 5, lane = tid & 31;
    int mbase = (warp >> 1) * 64, nbase = (warp & 1) * 64;   // 2m x 2n warps
    int rowsel = (lane & 7) + 8 * ((lane >> 3) & 1);
    int khalf16 = (lane >> 4) * 16;

    sbias[tid] = b1[(size_t)e * F_DIM + n0 + tid];

    float acc[4][8][4];
#pragma unroll
    for (int mt = 0; mt < 4; mt++)
#pragma unroll
        for (int nt = 0; nt < 8; nt++)
#pragma unroll
            for (int i = 0; i < 4; i++) acc[mt][nt][i] = 0.f;

    const __half* A  = g_xg + (size_t)(off + m0) * D_DIM;
    const __half* Bw = g_w1h + (size_t)e * F_DIM * D_DIM + (size_t)n0 * D_DIM;

    gemm_mainloop(s0, A, Bw, D_DIM, D_DIM / BK, tid,
                  mbase, nbase, rowsel, khalf16, acc);

    int grp = lane >> 2, q = lane & 3;
#pragma unroll
    for (int mt = 0; mt < 4; mt++) {
        int r0 = m0 + mbase + mt * 16 + grp;
#pragma unroll
        for (int nt = 0; nt < 8; nt++) {
            int c = nbase + nt * 8 + q * 2;
            float bv0 = sbias[c], bv1 = sbias[c + 1];
            if (r0 < len) {
                __half2 h2 = __floats2half2_rn(siluf(acc[mt][nt][0] + bv0),
                                               siluf(acc[mt][nt][1] + bv1));
                *(uint32_t*)(g_h + (size_t)(off + r0) * F_DIM + n0 + c) =
                    *(uint32_t*)&h2;
            }
            if (r0 + 8 < len) {
                __half2 h2 = __floats2half2_rn(siluf(acc[mt][nt][2] + bv0),
                                               siluf(acc[mt][nt][3] + bv1));
                *(uint32_t*)(g_h + (size_t)(off + r0 + 8) * F_DIM + n0 + c) =
                    *(uint32_t*)&h2;
            }
        }
    }
}

// ---------------- kernel 6: GEMM2  y += gate * (h @ W2h^T + b2) -------------
__global__ __launch_bounds__(NTHR, 2) void k_gemm2(const float* __restrict__ b2,
                                                   float* __restrict__ out) {
    int e   = blockIdx.z;
    int len = g_counts[e];
    int m0  = blockIdx.y * BM;
    if (m0 >= len) return;
    int n0  = blockIdx.x * BN;
    int off = g_offsets[e];

    extern __shared__ char smraw[];
    __shared__ float sbias[BN];
    uint32_t s0 = (uint32_t)__cvta_generic_to_shared(smraw);
    s0 = (s0 + 1023u) & ~1023u;

    int tid = threadIdx.x, warp = tid >> 5, lane = tid & 31;
    int mbase = (warp >> 1) * 64, nbase = (warp & 1) * 64;
    int rowsel = (lane & 7) + 8 * ((lane >> 3) & 1);
    int khalf16 = (lane >> 4) * 16;

    sbias[tid] = b2[(size_t)e * D_DIM + n0 + tid];

    float acc[4][8][4];
#pragma unroll
    for (int mt = 0; mt < 4; mt++)
#pragma unroll
        for (int nt = 0; nt < 8; nt++)
#pragma unroll
            for (int i = 0; i < 4; i++) acc[mt][nt][i] = 0.f;

    const __half* A  = g_h + (size_t)(off + m0) * F_DIM;
    const __half* Bw = g_w2h + (size_t)e * D_DIM * F_DIM + (size_t)n0 * F_DIM;

    gemm_mainloop(s0, A, Bw, F_DIM, F_DIM / BK, tid,
                  mbase, nbase, rowsel, khalf16, acc);

    int grp = lane >> 2, q = lane & 3;
#pragma unroll
    for (int mt = 0; mt < 4; mt++) {
        int r0 = m0 + mbase + mt * 16 + grp;
#pragma unroll
        for (int rr = 0; rr < 2; rr++) {
            int r = r0 + rr * 8;
            if (r >= len) continue;
            int slot = off + r;
            int tok  = g_token_of_slot[slot];
            float g  = g_gate_of_slot[slot];
            float* yrow = out + (size_t)tok * D_DIM + n0;
#pragma unroll
            for (int nt = 0; nt < 8; nt++) {
                int c = nbase + nt * 8 + q * 2;
                atomicAdd(&yrow[c],     g * (acc[mt][nt][rr * 2 + 0] + sbias[c]));
                atomicAdd(&yrow[c + 1], g * (acc[mt][nt][rr * 2 + 1] + sbias[c + 1]));
            }
        }
    }
}

// ---------------- launch ----------------
extern "C" void kernel_launch(void* const* d_in, const int* in_sizes, int n_in,
                              void* d_out, int out_size) {
    const float* x  = (const float*)d_in[0];
    const float* Wr = (const float*)d_in[1];
    const float* br = (const float*)d_in[2];
    const float* W1 = (const float*)d_in[3];
    const float* b1 = (const float*)d_in[4];
    const float* W2 = (const float*)d_in[5];
    const float* b2 = (const float*)d_in[6];
    float* out = (float*)d_out;

    static bool attr_set = false;
    if (!attr_set) {
        cudaFuncSetAttribute(k_gemm1, cudaFuncAttributeMaxDynamicSharedMemorySize,
                             SMEM_ALLOC);
        cudaFuncSetAttribute(k_gemm2, cudaFuncAttributeMaxDynamicSharedMemorySize,
                             SMEM_ALLOC);
        attr_set = true;
    }

    k_router<<<T_TOK / 8, 256>>>(x, Wr, br);
    k_sched<<<1, 512>>>();
    k_prep<<<NSLOT, 256>>>(x, W1, out);
    k_gemm1<<<dim3(F_DIM / BN, NSLOT / BM, E_NUM), NTHR, SMEM_ALLOC>>>(b1);
    k_cw2<<<8192, 256>>>(W2);
    k_gemm2<<<dim3(D_DIM / BN, NSLOT / BM, E_NUM), NTHR, SMEM_ALLOC>>>(b2, out);
}

// round 15
// speedup vs baseline: 1.0252x; 1.0252x over previous
#include <cuda_runtime.h>
#include <cuda_fp16.h>
#include <cstdint>

// Problem constants
#define T_TOK 4096
#define D_DIM 1024
#define E_NUM 8
#define F_DIM 4096
#define NSLOT (T_TOK * 2)
#define PAD_ROWS 256

// GEMM config: 128x64 CTA tile, 128 threads (4 warps, warp tile 64x32), 4 CTAs/SM
#define BM 128
#define BN 64
#define BK 32
#define SA 40
#define NTHR 128
#define A_TILE_B (BM * SA * 2)     // 10240 B
#define B_TILE_B (BN * SA * 2)     // 5120 B
#define STAGE_B (A_TILE_B + B_TILE_B)  // 15360 B
#define NSTAGE 3
#define SMEM_ALLOC (NSTAGE * STAGE_B + 1024)   // 47104 B

// ---------------- static scratch ----------------
__device__ __half g_xg[(size_t)(NSLOT + PAD_ROWS) * D_DIM];
__device__ __half g_h[(size_t)(NSLOT + PAD_ROWS) * F_DIM];
__device__ __half g_w1h[(size_t)E_NUM * F_DIM * D_DIM];
__device__ __half g_w2h[(size_t)E_NUM * D_DIM * F_DIM];
__device__ int    g_tok_e[NSLOT];
__device__ float  g_tok_g[NSLOT];
__device__ int    g_counts[E_NUM];
__device__ int    g_offsets[E_NUM];
__device__ int    g_token_of_slot[NSLOT];
__device__ float  g_gate_of_slot[NSLOT];

__device__ __forceinline__ float siluf(float v) { return v / (1.f + __expf(-v)); }

// ---------------- PTX helpers ----------------
__device__ __forceinline__ void cp16(uint32_t dst, const void* src) {
    asm volatile("cp.async.cg.shared.global [%0], [%1], 16;\n" :: "r"(dst), "l"(src));
}
__device__ __forceinline__ void cp_commit() { asm volatile("cp.async.commit_group;\n"); }
template <int N> __device__ __forceinline__ void cp_wait() {
    asm volatile("cp.async.wait_group %0;\n" :: "n"(N));
}
__device__ __forceinline__ void ldm_x4(uint32_t r[4], uint32_t addr) {
    asm volatile("ldmatrix.sync.aligned.m8n8.x4.shared.b16 {%0,%1,%2,%3}, [%4];"
                 : "=r"(r[0]), "=r"(r[1]), "=r"(r[2]), "=r"(r[3]) : "r"(addr));
}
__device__ __forceinline__ void mma16816(float c[4],
                                         const uint32_t a[4],
                                         const uint32_t b[2]) {
    asm volatile(
        "mma.sync.aligned.m16n8k16.row.col.f32.f16.f16.f32 "
        "{%0,%1,%2,%3}, {%4,%5,%6,%7}, {%8,%9}, {%0,%1,%2,%3};\n"
        : "+f"(c[0]), "+f"(c[1]), "+f"(c[2]), "+f"(c[3])
        : "r"(a[0]), "r"(a[1]), "r"(a[2]), "r"(a[3]), "r"(b[0]), "r"(b[1]));
}

// ---------------- kernel 1: router ----------------
__global__ void k_router(const float* __restrict__ x,
                         const float* __restrict__ Wr,
                         const float* __restrict__ br) {
    int warp = threadIdx.x >> 5, lane = threadIdx.x & 31;
    int t = blockIdx.x * 8 + warp;
    if (t >= T_TOK) return;

    const float4* xr = (const float4*)(x + (size_t)t * D_DIM);
    float acc[E_NUM];
#pragma unroll
    for (int e = 0; e < E_NUM; e++) acc[e] = 0.f;

    for (int i = lane; i < D_DIM / 4; i += 32) {
        float4 xv = xr[i];
#pragma unroll
        for (int e = 0; e < E_NUM; e++) {
            float4 wv = ((const float4*)(Wr + (size_t)e * D_DIM))[i];
            acc[e] += xv.x * wv.x + xv.y * wv.y + xv.z * wv.z + xv.w * wv.w;
        }
    }
#pragma unroll
    for (int e = 0; e < E_NUM; e++) {
#pragma unroll
        for (int off = 16; off > 0; off >>= 1)
            acc[e] += __shfl_down_sync(0xffffffffu, acc[e], off);
    }
    if (lane == 0) {
        float l[E_NUM];
#pragma unroll
        for (int e = 0; e < E_NUM; e++) l[e] = acc[e] + br[e];
        int i1 = 0;
#pragma unroll
        for (int e = 1; e < E_NUM; e++) if (l[e] > l[i1]) i1 = e;
        int i2 = (i1 == 0) ? 1 : 0;
#pragma unroll
        for (int e = 0; e < E_NUM; e++)
            if (e != i1 && l[e] > l[i2]) i2 = e;
        float d  = l[i2] - l[i1];
        float e2 = __expf(d);
        float inv = 1.f / (1.f + e2);
        g_tok_e[2 * t]     = i1; g_tok_g[2 * t]     = inv;
        g_tok_e[2 * t + 1] = i2; g_tok_g[2 * t + 1] = e2 * inv;
    }
}

// ---------------- kernel 2: sched (counts + offsets + assign; 1 block) -----
__global__ void k_sched() {
    __shared__ int cnt[E_NUM], offs[E_NUM], cur[E_NUM];
    int tid = threadIdx.x;
    if (tid < E_NUM) { cnt[tid] = 0; cur[tid] = 0; }
    __syncthreads();
    for (int s = tid; s < NSLOT; s += blockDim.x)
        atomicAdd(&cnt[g_tok_e[s]], 1);
    __syncthreads();
    if (tid == 0) {
        int o = 0;
        for (int e = 0; e < E_NUM; e++) {
            offs[e] = o;
            g_offsets[e] = o;
            g_counts[e] = cnt[e];
            o += cnt[e];
        }
    }
    __syncthreads();
    for (int t = tid; t < T_TOK; t += blockDim.x) {
#pragma unroll
        for (int j = 0; j < 2; j++) {
            int e = g_tok_e[2 * t + j];
            int p = atomicAdd(&cur[e], 1);
            int slot = offs[e] + p;
            g_token_of_slot[slot] = t;
            g_gate_of_slot[slot]  = g_tok_g[2 * t + j];
        }
    }
}

// ---------------- kernel 3: prep (zero out + gather + W1 convert) ----------
__global__ __launch_bounds__(256) void k_prep(const float* __restrict__ x,
                                              const float* __restrict__ W1,
                                              float* __restrict__ out) {
    int b = blockIdx.x, tid = threadIdx.x;
    if (tid < 128)
        ((float4*)out)[(size_t)b * 128 + tid] = make_float4(0.f, 0.f, 0.f, 0.f);
    {
        int tok = g_token_of_slot[b];
        float4 v = ((const float4*)(x + (size_t)tok * D_DIM))[tid];
        __half2 lo = __floats2half2_rn(v.x, v.y);
        __half2 hi = __floats2half2_rn(v.z, v.w);
        uint2 u; u.x = *(uint32_t*)&lo; u.y = *(uint32_t*)&hi;
        ((uint2*)(g_xg + (size_t)b * D_DIM))[tid] = u;
    }
#pragma unroll
    for (int j = 0; j < 4; j++) {
        size_t i = (size_t)b * 1024 + j * 256 + tid;
        float4 v = ((const float4*)W1)[i];
        __half2 lo = __floats2half2_rn(v.x, v.y);
        __half2 hi = __floats2half2_rn(v.z, v.w);
        uint2 u; u.x = *(uint32_t*)&lo; u.y = *(uint32_t*)&hi;
        ((uint2*)g_w1h)[i] = u;
    }
}

// ---------------- kernel 5: convert W2 ----------------
__global__ __launch_bounds__(256) void k_cw2(const float* __restrict__ W2) {
    size_t n4 = (size_t)E_NUM * D_DIM * F_DIM / 4;
    for (size_t i = (size_t)blockIdx.x * blockDim.x + threadIdx.x; i < n4;
         i += (size_t)gridDim.x * blockDim.x) {
        float4 v = ((const float4*)W2)[i];
        __half2 lo = __floats2half2_rn(v.x, v.y);
        __half2 hi = __floats2half2_rn(v.z, v.w);
        uint2 u; u.x = *(uint32_t*)&lo; u.y = *(uint32_t*)&hi;
        ((uint2*)g_w2h)[i] = u;
    }
}

// ---------------- GEMM core ----------------
// fill one stage: A (128 x 32 halves) + B (64 x 32 halves), rows padded SA=40
__device__ __forceinline__ void fill_stage(uint32_t sbase,
                                           const __half* A, const __half* Bw,
                                           int k0, int ldk, int tid) {
#pragma unroll
    for (int it = 0; it < 4; it++) {
        int i = tid + it * NTHR;          // 0..511
        int r = i >> 2, c = i & 3;
        cp16(sbase + (uint32_t)(r * SA + c * 8) * 2,
             A + (size_t)r * ldk + k0 + c * 8);
    }
#pragma unroll
    for (int it = 0; it < 2; it++) {
        int i = tid + it * NTHR;          // 0..255
        int r = i >> 2, c = i & 3;
        cp16(sbase + A_TILE_B + (uint32_t)(r * SA + c * 8) * 2,
             Bw + (size_t)r * ldk + k0 + c * 8);
    }
}

// compute one BK=32 stage; warp tile 64x32 (R13-proven mapping)
__device__ __forceinline__ void compute_stage(uint32_t sbase, int mbase, int nbase,
                                              int rowsel, int khalf16,
                                              float acc[4][4][4]) {
    uint32_t abase = sbase, bbase = sbase + A_TILE_B;
#pragma unroll
    for (int kk = 0; kk < 2; kk++) {
        int kbyte = kk * 32 + khalf16;
        uint32_t a[4][4];
#pragma unroll
        for (int mt = 0; mt < 4; mt++) {
            int row = mbase + mt * 16 + rowsel;
            ldm_x4(a[mt], abase + row * (SA * 2) + kbyte);
        }
        uint32_t b[4][2];
#pragma unroll
        for (int ntp = 0; ntp < 2; ntp++) {
            int row = nbase + ntp * 16 + rowsel;
            uint32_t t[4];
            ldm_x4(t, bbase + row * (SA * 2) + kbyte);
            b[2 * ntp][0] = t[0]; b[2 * ntp + 1][0] = t[1];
            b[2 * ntp][1] = t[2]; b[2 * ntp + 1][1] = t[3];
        }
#pragma unroll
        for (int mt = 0; mt < 4; mt++)
#pragma unroll
            for (int nt = 0; nt < 4; nt++)
                mma16816(acc[mt][nt], a[mt], b[nt]);
    }
}

// 3-stage, one __syncthreads per K-step (R8-proven schedule)
__device__ __forceinline__ void gemm_mainloop(uint32_t s0,
                                              const __half* A, const __half* Bw,
                                              int ldk, int NK, int tid,
                                              int mbase, int nbase,
                                              int rowsel, int khalf16,
                                              float acc[4][4][4]) {
    fill_stage(s0, A, Bw, 0, ldk, tid);
    cp_commit();
    fill_stage(s0 + STAGE_B, A, Bw, BK, ldk, tid);
    cp_commit();
    int buf = 0;
    for (int it = 0; it < NK; it++) {
        if (it + 1 < NK) cp_wait<1>(); else cp_wait<0>();
        __syncthreads();
        if (it + 2 < NK) {
            int nb = buf + 2; if (nb >= NSTAGE) nb -= NSTAGE;
            fill_stage(s0 + nb * STAGE_B, A, Bw, (it + 2) * BK, ldk, tid);
            cp_commit();
        }
        compute_stage(s0 + buf * STAGE_B, mbase, nbase, rowsel, khalf16, acc);
        buf++; if (buf == NSTAGE) buf = 0;
    }
}

// ---------------- kernel 4: GEMM1  h = silu(xg @ W1h^T + b1) ----------------
__global__ __launch_bounds__(NTHR, 4) void k_gemm1(const float* __restrict__ b1) {
    int e   = blockIdx.z;
    int len = g_counts[e];
    int m0  = blockIdx.y * BM;
    if (m0 >= len) return;
    int n0  = blockIdx.x * BN;
    int off = g_offsets[e];

    extern __shared__ char smraw[];
    __shared__ float sbias[BN];
    uint32_t s0 = (uint32_t)__cvta_generic_to_shared(smraw);
    s0 = (s0 + 1023u) & ~1023u;

    int tid = threadIdx.x, warp = tid >> 5, lane = tid & 31;
    int mbase = (warp >> 1) * 64, nbase = (warp & 1) * 32;   // 2m x 2n warps
    int rowsel = (lane & 7) + 8 * ((lane >> 3) & 1);
    int khalf16 = (lane >> 4) * 16;

    if (tid < BN) sbias[tid] = b1[(size_t)e * F_DIM + n0 + tid];

    float acc[4][4][4];
#pragma unroll
    for (int mt = 0; mt < 4; mt++)
#pragma unroll
        for (int nt = 0; nt < 4; nt++)
#pragma unroll
            for (int i = 0; i < 4; i++) acc[mt][nt][i] = 0.f;

    const __half* A  = g_xg + (size_t)(off + m0) * D_DIM;
    const __half* Bw = g_w1h + (size_t)e * F_DIM * D_DIM + (size_t)n0 * D_DIM;

    gemm_mainloop(s0, A, Bw, D_DIM, D_DIM / BK, tid,
                  mbase, nbase, rowsel, khalf16, acc);

    int grp = lane >> 2, q = lane & 3;
#pragma unroll
    for (int mt = 0; mt < 4; mt++) {
        int r0 = m0 + mbase + mt * 16 + grp;
#pragma unroll
        for (int nt = 0; nt < 4; nt++) {
            int c = nbase + nt * 8 + q * 2;
            float bv0 = sbias[c], bv1 = sbias[c + 1];
            if (r0 < len) {
                __half2 h2 = __floats2half2_rn(siluf(acc[mt][nt][0] + bv0),
                                               siluf(acc[mt][nt][1] + bv1));
                *(uint32_t*)(g_h + (size_t)(off + r0) * F_DIM + n0 + c) =
                    *(uint32_t*)&h2;
            }
            if (r0 + 8 < len) {
                __half2 h2 = __floats2half2_rn(siluf(acc[mt][nt][2] + bv0),
                                               siluf(acc[mt][nt][3] + bv1));
                *(uint32_t*)(g_h + (size_t)(off + r0 + 8) * F_DIM + n0 + c) =
                    *(uint32_t*)&h2;
            }
        }
    }
}

// ---------------- kernel 6: GEMM2  y += gate * (h @ W2h^T + b2) -------------
__global__ __launch_bounds__(NTHR, 4) void k_gemm2(const float* __restrict__ b2,
                                                   float* __restrict__ out) {
    int e   = blockIdx.z;
    int len = g_counts[e];
    int m0  = blockIdx.y * BM;
    if (m0 >= len) return;
    int n0  = blockIdx.x * BN;
    int off = g_offsets[e];

    extern __shared__ char smraw[];
    __shared__ float sbias[BN];
    uint32_t s0 = (uint32_t)__cvta_generic_to_shared(smraw);
    s0 = (s0 + 1023u) & ~1023u;

    int tid = threadIdx.x, warp = tid >> 5, lane = tid & 31;
    int mbase = (warp >> 1) * 64, nbase = (warp & 1) * 32;
    int rowsel = (lane & 7) + 8 * ((lane >> 3) & 1);
    int khalf16 = (lane >> 4) * 16;

    if (tid < BN) sbias[tid] = b2[(size_t)e * D_DIM + n0 + tid];

    float acc[4][4][4];
#pragma unroll
    for (int mt = 0; mt < 4; mt++)
#pragma unroll
        for (int nt = 0; nt < 4; nt++)
#pragma unroll
            for (int i = 0; i < 4; i++) acc[mt][nt][i] = 0.f;

    const __half* A  = g_h + (size_t)(off + m0) * F_DIM;
    const __half* Bw = g_w2h + (size_t)e * D_DIM * F_DIM + (size_t)n0 * F_DIM;

    gemm_mainloop(s0, A, Bw, F_DIM, F_DIM / BK, tid,
                  mbase, nbase, rowsel, khalf16, acc);

    int grp = lane >> 2, q = lane & 3;
#pragma unroll
    for (int mt = 0; mt < 4; mt++) {
        int r0 = m0 + mbase + mt * 16 + grp;
#pragma unroll
        for (int rr = 0; rr < 2; rr++) {
            int r = r0 + rr * 8;
            if (r >= len) continue;
            int slot = off + r;
            int tok  = g_token_of_slot[slot];
            float g  = g_gate_of_slot[slot];
            float* yrow = out + (size_t)tok * D_DIM + n0;
#pragma unroll
            for (int nt = 0; nt < 4; nt++) {
                int c = nbase + nt * 8 + q * 2;
                atomicAdd(&yrow[c],     g * (acc[mt][nt][rr * 2 + 0] + sbias[c]));
                atomicAdd(&yrow[c + 1], g * (acc[mt][nt][rr * 2 + 1] + sbias[c + 1]));
            }
        }
    }
}

// ---------------- launch ----------------
extern "C" void kernel_launch(void* const* d_in, const int* in_sizes, int n_in,
                              void* d_out, int out_size) {
    const float* x  = (const float*)d_in[0];
    const float* Wr = (const float*)d_in[1];
    const float* br = (const float*)d_in[2];
    const float* W1 = (const float*)d_in[3];
    const float* b1 = (const float*)d_in[4];
    const float* W2 = (const float*)d_in[5];
    const float* b2 = (const float*)d_in[6];
    float* out = (float*)d_out;

    static bool attr_set = false;
    if (!attr_set) {
        cudaFuncSetAttribute(k_gemm1, cudaFuncAttributeMaxDynamicSharedMemorySize,
                             SMEM_ALLOC);
        cudaFuncSetAttribute(k_gemm2, cudaFuncAttributeMaxDynamicSharedMemorySize,
                             SMEM_ALLOC);
        attr_set = true;
    }

    k_router<<<T_TOK / 8, 256>>>(x, Wr, br);
    k_sched<<<1, 512>>>();
    k_prep<<<NSLOT, 256>>>(x, W1, out);
    k_gemm1<<<dim3(F_DIM / BN, NSLOT / BM, E_NUM), NTHR, SMEM_ALLOC>>>(b1);
    k_cw2<<<8192, 256>>>(W2);
    k_gemm2<<<dim3(D_DIM / BN, NSLOT / BM, E_NUM), NTHR, SMEM_ALLOC>>>(b2, out);
}